// round 2
// baseline (speedup 1.0000x reference)
#include <cuda_runtime.h>

// GaussianEdgeGuide, fused 2-iteration edge-guided 3x3 stencil.
//
// Algebra: softmax over the 9 neighborhood positions of
//   -theta*(edge_center + edge_neighbor - max_edge)
// has edge_center and max_edge constant along the softmax axis, so
//   weight_k(q) = E(q+d_k) / S(q),   E(x) = exp(-theta*edge(x)) (E=1 outside),
//   S(q) = sum_k E(q+d_k).
// One iteration: mask'(q) = box3(mask*E)(q) / S(q)   (mask zero-padded).
// Two iterations fused per 32x32 tile with halo 2, weights shared over 19 ch.

#define NB   8
#define NC   19
#define HW   256
#define TILE 32
#define EW   36   // E / P tile extent (TILE + 4)
#define MW   34   // intermediate extent (TILE + 2)
#define ES   37   // padded row strides (odd -> bank spread)
#define MS   35
#define NTHREADS 256

__global__ __launch_bounds__(NTHREADS, 4)
void geg_kernel(const float* __restrict__ mask,
                const float* __restrict__ edge,
                float* __restrict__ out)
{
    __shared__ float sE  [EW * ES];  // exp(-theta*edge), 1 outside image
    __shared__ float sP  [EW * ES];  // mask * E (0 outside image)
    __shared__ float sInv[MW * MS];  // 1 / S
    __shared__ float sIE [MW * MS];  // invS * E at center (0 outside image)
    __shared__ float sM  [MW * MS];  // iter-1 result * E  (0 outside image)

    const int tid = threadIdx.x;
    const int bx = blockIdx.x, by = blockIdx.y, n = blockIdx.z;
    const int h0 = by * TILE, w0 = bx * TILE;

    // ---- Phase 0: E tile (once per CTA) ----
    const float* eimg = edge + (n << 16);
    for (int idx = tid; idx < EW * EW; idx += NTHREADS) {
        int i = idx / EW, j = idx - i * EW;
        int gy = h0 - 2 + i, gx = w0 - 2 + j;
        float e = 1.0f;  // exp(-theta * 0) for zero-padded border
        if ((unsigned)gy < (unsigned)HW && (unsigned)gx < (unsigned)HW)
            e = __expf(-40.0f * eimg[(gy << 8) + gx]);
        sE[i * ES + j] = e;
    }
    __syncthreads();

    // ---- Phase 1: 1/S and invS*E_center (once per CTA) ----
    for (int idx = tid; idx < MW * MW; idx += NTHREADS) {
        int a = idx / MW, b = idx - a * MW;
        const float* p = &sE[a * ES + b];
        float s = p[0]        + p[1]          + p[2]
                + p[ES]       + p[ES + 1]     + p[ES + 2]
                + p[2 * ES]   + p[2 * ES + 1] + p[2 * ES + 2];
        float inv = __fdividef(1.0f, s);
        sInv[a * MS + b] = inv;
        int gy = h0 - 1 + a, gx = w0 - 1 + b;
        bool in = (unsigned)gy < (unsigned)HW && (unsigned)gx < (unsigned)HW;
        sIE[a * MS + b] = in ? inv * p[ES + 1] : 0.0f;
    }
    // first __syncthreads() inside the channel loop covers phase-1 completion

    const int tj = tid & 31, tb = tid >> 5;

    for (int c = 0; c < NC; ++c) {
        const float* mch = mask + (((size_t)(n * NC + c)) << 16);
        float*       och = out  + (((size_t)(n * NC + c)) << 16);

        // protects: phase-1 arrays ready (c==0); previous channel's output
        // phase finished reading sM before we overwrite it below.
        __syncthreads();

        // ---- P = mask * E (halo tile) ----
        for (int idx = tid; idx < EW * EW; idx += NTHREADS) {
            int i = idx / EW, j = idx - i * EW;
            int gy = h0 - 2 + i, gx = w0 - 2 + j;
            float m = 0.0f;  // zero-padded mask -> P = 0 outside
            if ((unsigned)gy < (unsigned)HW && (unsigned)gx < (unsigned)HW)
                m = mch[(gy << 8) + gx] * sE[i * ES + j];
            sP[i * ES + j] = m;
        }
        __syncthreads();

        // ---- iteration 1: sM = box3(P) * invS * E  (already * E for iter 2) ----
        for (int idx = tid; idx < MW * MW; idx += NTHREADS) {
            int a = idx / MW, b = idx - a * MW;
            const float* p = &sP[a * ES + b];
            float s = p[0]        + p[1]          + p[2]
                    + p[ES]       + p[ES + 1]     + p[ES + 2]
                    + p[2 * ES]   + p[2 * ES + 1] + p[2 * ES + 2];
            sM[a * MS + b] = s * sIE[a * MS + b];
        }
        __syncthreads();

        // ---- iteration 2: out = box3(sM) * invS, coalesced 32-wide stores ----
        #pragma unroll
        for (int k = 0; k < 4; ++k) {
            int ti = tb + 8 * k;
            const float* p = &sM[ti * MS + tj];
            float s = p[0]        + p[1]          + p[2]
                    + p[MS]       + p[MS + 1]     + p[MS + 2]
                    + p[2 * MS]   + p[2 * MS + 1] + p[2 * MS + 2];
            och[((h0 + ti) << 8) + (w0 + tj)] = s * sInv[(ti + 1) * MS + tj + 1];
        }
    }
}

extern "C" void kernel_launch(void* const* d_in, const int* in_sizes, int n_in,
                              void* d_out, int out_size)
{
    const float* mask = (const float*)d_in[0];
    const float* edge = (const float*)d_in[1];
    // d_in[2] = iter_n (device int) is fixed at 2 by the problem setup; the
    // kernel fuses exactly 2 iterations.
    (void)in_sizes; (void)n_in; (void)out_size;

    dim3 grid(HW / TILE, HW / TILE, NB);  // 8 x 8 x 8 = 512 CTAs
    geg_kernel<<<grid, NTHREADS>>>(mask, edge, (float*)d_out);
}

// round 3
// speedup vs baseline: 1.1197x; 1.1197x over previous
#include <cuda_runtime.h>

// GaussianEdgeGuide, 2-kernel formulation.
//
// Algebra: softmax over the 9 neighborhood positions of
//   -theta*(edge_center + edge_neighbor - max_edge)
// has edge_center and max_edge constant along the softmax axis, so
//   weight_k(q) = E(q+d_k) / S(q),   E(x) = exp(-theta*edge(x)) (E=1 outside),
//   S(q) = sum_k E(q+d_k).
// One iteration: mask'(q) = box3(mask*E)(q) / S(q)   (mask zero-padded).
//
// Kernel 1 (prep): per pixel, E = exp(-40*edge), W = 1/box3(E), IE = W*E.
// Kernel 2 (stencil): one CTA per (batch, channel, 32x32 tile); two fused
// box3 passes through shared memory. 9728 independent CTAs -> barrier
// stalls of one CTA hidden by others (R2 kernel serialized 19 channels
// behind 57 barriers per CTA; issue was only 37%).

#define NB   8
#define NC   19
#define HW   256
#define NPIX (HW * HW)          // 65536
#define TILE 32
#define EW   36                 // P-tile extent (TILE + 4)
#define MW   34                 // intermediate extent (TILE + 2)
#define ES   37                 // padded strides (odd -> bank spread)
#define MS   35
#define PS   35                 // prep sE stride (34 + 1)

__device__ float g_E [NB * NPIX];   // exp(-40*edge)
__device__ float g_W [NB * NPIX];   // 1 / box3(E)
__device__ float g_IE[NB * NPIX];   // W * E

// ---------------------------------------------------------------------------
// Kernel 1: per-pixel E, W, IE.
// ---------------------------------------------------------------------------
__global__ __launch_bounds__(256, 4)
void geg_prep(const float* __restrict__ edge)
{
    __shared__ float sE[MW * PS];   // 34x34 E with halo 1, E=1 outside image

    const int tid = threadIdx.x;
    const int h0 = blockIdx.y * TILE, w0 = blockIdx.x * TILE;
    const int n  = blockIdx.z;
    const float* eimg = edge + (n << 16);

    for (int idx = tid; idx < MW * MW; idx += 256) {
        int i = idx / MW, j = idx - i * MW;
        int gy = h0 - 1 + i, gx = w0 - 1 + j;
        float e = 1.0f;  // exp(-40 * 0) at zero-padded border
        if ((unsigned)gy < (unsigned)HW && (unsigned)gx < (unsigned)HW)
            e = __expf(-40.0f * eimg[(gy << 8) + gx]);
        sE[i * PS + j] = e;
    }
    __syncthreads();

    const int tj = tid & 31, tb = tid >> 5;
    #pragma unroll
    for (int k = 0; k < 4; ++k) {
        int ti = tb + 8 * k;
        const float* p = &sE[ti * PS + tj];
        float s = p[0]        + p[1]          + p[2]
                + p[PS]       + p[PS + 1]     + p[PS + 2]
                + p[2 * PS]   + p[2 * PS + 1] + p[2 * PS + 2];
        float w  = __fdividef(1.0f, s);
        float ec = p[PS + 1];
        int g = (n << 16) + ((h0 + ti) << 8) + (w0 + tj);
        g_E [g] = ec;
        g_W [g] = w;
        g_IE[g] = w * ec;
    }
}

// ---------------------------------------------------------------------------
// Kernel 2: one (batch, channel, tile) per CTA; two fused box3 passes.
// ---------------------------------------------------------------------------
__global__ __launch_bounds__(256, 4)
void geg_stencil(const float* __restrict__ mask,
                 float* __restrict__ out)
{
    __shared__ float sP[EW * ES];   // mask * E (0 outside image)
    __shared__ float sM[MW * MS];   // iter-1 result * E * W (0 outside image)

    const int tid = threadIdx.x;
    const int h0 = blockIdx.y * TILE, w0 = blockIdx.x * TILE;
    const int z  = blockIdx.z;            // n * NC + c
    const int n  = z / NC;

    const float* mch = mask + ((size_t)z << 16);
    float*       och = out  + ((size_t)z << 16);
    const float* Eb  = g_E  + (n << 16);
    const float* IEb = g_IE + (n << 16);
    const float* Wb  = g_W  + (n << 16);

    // ---- P = mask * E over the 36x36 halo tile ----
    for (int idx = tid; idx < EW * EW; idx += 256) {
        int i = idx / EW, j = idx - i * EW;
        int gy = h0 - 2 + i, gx = w0 - 2 + j;
        float m = 0.0f;  // zero-padded mask -> P = 0 outside
        if ((unsigned)gy < (unsigned)HW && (unsigned)gx < (unsigned)HW) {
            int g = (gy << 8) + gx;
            m = mch[g] * Eb[g];
        }
        sP[i * ES + j] = m;
    }
    __syncthreads();

    // ---- iteration 1: sM = box3(P) * IE  (IE = W*E, pre-scaled for iter 2) ----
    for (int idx = tid; idx < MW * MW; idx += 256) {
        int a = idx / MW, b = idx - a * MW;
        const float* p = &sP[a * ES + b];
        float s = p[0]        + p[1]          + p[2]
                + p[ES]       + p[ES + 1]     + p[ES + 2]
                + p[2 * ES]   + p[2 * ES + 1] + p[2 * ES + 2];
        int gy = h0 - 1 + a, gx = w0 - 1 + b;
        float v = 0.0f;  // iterated mask is 0 outside the image
        if ((unsigned)gy < (unsigned)HW && (unsigned)gx < (unsigned)HW)
            v = s * IEb[(gy << 8) + gx];
        sM[a * MS + b] = v;
    }
    __syncthreads();

    // ---- iteration 2: out = box3(sM) * W, coalesced 32-wide stores ----
    const int tj = tid & 31, tb = tid >> 5;
    #pragma unroll
    for (int k = 0; k < 4; ++k) {
        int ti = tb + 8 * k;
        const float* p = &sM[ti * MS + tj];
        float s = p[0]        + p[1]          + p[2]
                + p[MS]       + p[MS + 1]     + p[MS + 2]
                + p[2 * MS]   + p[2 * MS + 1] + p[2 * MS + 2];
        int g = ((h0 + ti) << 8) + (w0 + tj);
        och[g] = s * Wb[g];
    }
}

extern "C" void kernel_launch(void* const* d_in, const int* in_sizes, int n_in,
                              void* d_out, int out_size)
{
    const float* mask = (const float*)d_in[0];
    const float* edge = (const float*)d_in[1];
    // d_in[2] = iter_n is fixed at 2 by the problem setup; 2 iterations fused.
    (void)in_sizes; (void)n_in; (void)out_size;

    dim3 gp(HW / TILE, HW / TILE, NB);        // 8 x 8 x 8
    geg_prep<<<gp, 256>>>(edge);

    dim3 gs(HW / TILE, HW / TILE, NB * NC);   // 8 x 8 x 152 = 9728 CTAs
    geg_stencil<<<gs, 256>>>(mask, (float*)d_out);
}